// round 6
// baseline (speedup 1.0000x reference)
#include <cuda_runtime.h>
#include <cstdint>
#include <math.h>

#define NE   8
#define DD   1024
#define FF   4096
#define TMAX 4096

// ---------------- device scratch ----------------
__device__ int   g_cnt[NE];
__device__ int   g_tok[NE * TMAX];
__device__ float g_wt [NE * TMAX];
__device__ float g_Xc [(size_t)TMAX * DD];          // tf32-rounded x (k-major)
__device__ float g_w1t[(size_t)NE * DD * FF];       // tf32 w1^T : [E][F][D]  (n-major)
__device__ float g_w3t[(size_t)NE * DD * FF];       // tf32 w3^T : [E][F][D]
__device__ float g_w2t[(size_t)NE * FF * DD];       // tf32 w2^T : [E][D][F]
__device__ float g_H  [(size_t)NE * TMAX * FF];     // SwiGLU acts (tf32-rounded)

// ---------------- helpers ----------------
__device__ __forceinline__ uint32_t smem_u32(const void* p) {
    uint32_t a;
    asm("{ .reg .u64 t; cvta.to.shared.u64 t, %1; cvt.u32.u64 %0, t; }" : "=r"(a) : "l"(p));
    return a;
}
__device__ __forceinline__ void cp16(uint32_t dst, const void* src) {
    asm volatile("cp.async.cg.shared.global [%0], [%1], 16;" :: "r"(dst), "l"(src));
}
__device__ __forceinline__ void cp_commit() { asm volatile("cp.async.commit_group;"); }
__device__ __forceinline__ void cp_wait1()  { asm volatile("cp.async.wait_group 1;"); }

__device__ __forceinline__ uint32_t to_tf32(float f) {
    uint32_t u;
    asm("cvt.rna.tf32.f32 %0, %1;" : "=r"(u) : "f"(f));
    return u;
}
__device__ __forceinline__ void mma8(float* c, uint32_t a0, uint32_t a1, uint32_t a2,
                                     uint32_t a3, uint32_t b0, uint32_t b1) {
    asm volatile(
        "mma.sync.aligned.m16n8k8.row.col.f32.tf32.tf32.f32 "
        "{%0,%1,%2,%3}, {%4,%5,%6,%7}, {%8,%9}, {%0,%1,%2,%3};"
        : "+f"(c[0]), "+f"(c[1]), "+f"(c[2]), "+f"(c[3])
        : "r"(a0), "r"(a1), "r"(a2), "r"(a3), "r"(b0), "r"(b1));
}
#define EL(v, i) (((const uint32_t*)&(v))[i])

// ---------------- small kernels ----------------
__global__ void zero_cnt_kernel() { if (threadIdx.x < NE) g_cnt[threadIdx.x] = 0; }

__global__ void conv_tf32_kernel(const float4* __restrict__ s, float4* __restrict__ d, int n4) {
    int i = blockIdx.x * blockDim.x + threadIdx.x;
    int stride = gridDim.x * blockDim.x;
    for (; i < n4; i += stride) {
        float4 v = s[i];
        uint4 o;
        o.x = to_tf32(v.x); o.y = to_tf32(v.y); o.z = to_tf32(v.z); o.w = to_tf32(v.w);
        d[i] = *(float4*)&o;
    }
}

// fused transpose + tf32 round: src [B][R][C] -> dst [B][C][R]
__global__ void trans_tf32_kernel(const float* __restrict__ src, float* __restrict__ dst,
                                  int R, int C) {
    __shared__ float t[32][33];
    int b  = blockIdx.z;
    int c0 = blockIdx.x * 32, r0 = blockIdx.y * 32;
    const float* s = src + (size_t)b * R * C;
    float* d = dst + (size_t)b * R * C;
    int tx = threadIdx.x & 31, ty = threadIdx.x >> 5;
#pragma unroll
    for (int i = 0; i < 32; i += 8) {
        float v = s[(size_t)(r0 + ty + i) * C + c0 + tx];
        t[ty + i][tx] = __uint_as_float(to_tf32(v));
    }
    __syncthreads();
#pragma unroll
    for (int i = 0; i < 32; i += 8)
        d[(size_t)(c0 + ty + i) * R + r0 + tx] = t[tx][ty + i];
}

__global__ void gate_kernel(const float* __restrict__ x,
                            const float* __restrict__ gw, int T) {
    int warp = (blockIdx.x * blockDim.x + threadIdx.x) >> 5;
    int lane = threadIdx.x & 31;
    if (warp >= T) return;
    const float* xr = x + (size_t)warp * DD;
    float acc[NE];
#pragma unroll
    for (int e = 0; e < NE; e++) acc[e] = 0.f;
    for (int d = lane; d < DD; d += 32) {
        float xv = xr[d];
        const float* g = gw + (size_t)d * NE;
#pragma unroll
        for (int e = 0; e < NE; e++) acc[e] += xv * g[e];
    }
#pragma unroll
    for (int e = 0; e < NE; e++)
#pragma unroll
        for (int off = 16; off > 0; off >>= 1)
            acc[e] += __shfl_xor_sync(0xffffffffu, acc[e], off);
    if (lane == 0) {
        int i0 = 0; float v0 = acc[0];
#pragma unroll
        for (int e = 1; e < NE; e++) if (acc[e] > v0) { v0 = acc[e]; i0 = e; }
        int i1 = -1; float v1 = -3.0e38f;
#pragma unroll
        for (int e = 0; e < NE; e++)
            if (e != i0 && acc[e] > v1) { v1 = acc[e]; i1 = e; }
        float t  = expf(v1 - v0);
        float w0 = 1.f / (1.f + t);
        float w1 = t / (1.f + t);
        int s0 = atomicAdd(&g_cnt[i0], 1);
        g_tok[i0 * TMAX + s0] = warp; g_wt[i0 * TMAX + s0] = w0;
        int s1 = atomicAdd(&g_cnt[i1], 1);
        g_tok[i1 * TMAX + s1] = warp; g_wt[i1 * TMAX + s1] = w1;
    }
}

// ======================= GEMM1: H = silu(X W1) * (X W3) * wgt =======================
// block 128x64, BK=32, 8 warps (4m x 2n), warp tile 32x32, dual accumulators.
// A smem [128 rows][36] k-contig; B smem [64 n][36] k-contig (from n-major weights).
// stage = 18432 + 2*9216 = 36864B; 2 stages = 72KB -> 2 CTAs/SM.
// Thread t's fragment words for ALL 4 k-steps are contiguous (words 8t..8t+7):
// 2x LDS.128 per row/col group per ktile; logical-k permutation is exact.
#define G1_STAGE_F 9216
#define G1_SMEM   (2 * 36864)

__global__ void __launch_bounds__(256, 2)
gemm1_mma(const float* __restrict__ Xc,
          const float* __restrict__ w1t,
          const float* __restrict__ w3t) {
    const int e    = blockIdx.z;
    const int cnt  = g_cnt[e];
    const int row0 = blockIdx.y * 128;
    if (row0 >= cnt) return;
    const int n0   = blockIdx.x * 64;

    extern __shared__ float sm[];
    const uint32_t sbase = smem_u32(sm);

    const int tid  = threadIdx.x;
    const int lane = tid & 31;
    const int wm   = (tid >> 5) & 3;     // warp m: 0..3
    const int wn   = (tid >> 5) >> 2;    // warp n: 0..1
    const int gId  = lane >> 2;          // 0..7
    const int tId  = lane & 3;           // 0..3

    // ---- cp.async source/dst precompute ----
    const float* asrc[4]; uint32_t adst[4];
#pragma unroll
    for (int j = 0; j < 4; j++) {
        int c = tid + 256 * j;
        int row = c >> 3, kc = c & 7;
        int rr = row0 + row; if (rr >= cnt) rr = cnt - 1;
        int tok = g_tok[e * TMAX + rr];
        asrc[j] = Xc + (size_t)tok * DD + kc * 4;
        adst[j] = 144u * row + 16u * kc;
    }
    const float* bsrc[4]; uint32_t bdst[4];
#pragma unroll
    for (int j = 0; j < 4; j++) {
        int c = tid + 256 * j;
        int mat = c >> 9, cc = c & 511;
        int n = cc >> 3, kc = cc & 7;
        const float* w = mat ? w3t : w1t;
        bsrc[j] = w + (size_t)e * DD * FF + (size_t)(n0 + n) * DD + kc * 4;
        bdst[j] = 18432u + (uint32_t)mat * 9216u + 144u * n + 16u * kc;
    }

#define G1_ISSUE(KT, S) do {                                        \
        uint32_t so_ = sbase + (uint32_t)(S) * 36864u;              \
        int k0_ = (KT) * 32;                                        \
        _Pragma("unroll")                                           \
        for (int j = 0; j < 4; j++) cp16(so_ + adst[j], asrc[j] + k0_); \
        _Pragma("unroll")                                           \
        for (int j = 0; j < 4; j++) cp16(so_ + bdst[j], bsrc[j] + k0_); \
    } while (0)

    G1_ISSUE(0, 0); cp_commit();
    G1_ISSUE(1, 1); cp_commit();

    float acc1[2][4][4], acc3[2][4][4];
#pragma unroll
    for (int mi = 0; mi < 2; mi++)
#pragma unroll
        for (int ni = 0; ni < 4; ni++)
#pragma unroll
            for (int q = 0; q < 4; q++) { acc1[mi][ni][q] = 0.f; acc3[mi][ni][q] = 0.f; }

    const int NKT = DD / 32;   // 32
    for (int kt = 0; kt < NKT; kt++) {
        cp_wait1();
        __syncthreads();
        const float* As = sm + (kt & 1) * G1_STAGE_F;
        const float* B1 = As + 4608;
        const float* B3 = As + 6912;

#pragma unroll
        for (int h = 0; h < 2; h++) {          // k-half: k-steps 2h, 2h+1
            const int kb = 8 * tId + 4 * h;
            uint4 qalo[2], qahi[2];
#pragma unroll
            for (int mi = 0; mi < 2; mi++) {
                int r = wm * 32 + mi * 16 + gId;
                qalo[mi] = *(const uint4*)(As + r * 36 + kb);
                qahi[mi] = *(const uint4*)(As + (r + 8) * 36 + kb);
            }
#pragma unroll
            for (int bh = 0; bh < 2; bh++) {   // n-half: ni = bh*2 + {0,1}
                uint4 qb1[2], qb3[2];
#pragma unroll
                for (int q = 0; q < 2; q++) {
                    int n = wn * 32 + (bh * 2 + q) * 8 + gId;
                    qb1[q] = *(const uint4*)(B1 + n * 36 + kb);
                    qb3[q] = *(const uint4*)(B3 + n * 36 + kb);
                }
#pragma unroll
                for (int j = 0; j < 2; j++) {
#pragma unroll
                    for (int mi = 0; mi < 2; mi++) {
                        uint32_t a0 = EL(qalo[mi], 2 * j),     a1 = EL(qahi[mi], 2 * j);
                        uint32_t a2 = EL(qalo[mi], 2 * j + 1), a3 = EL(qahi[mi], 2 * j + 1);
#pragma unroll
                        for (int q = 0; q < 2; q++) {
                            mma8(acc1[mi][bh * 2 + q], a0, a1, a2, a3,
                                 EL(qb1[q], 2 * j), EL(qb1[q], 2 * j + 1));
                            mma8(acc3[mi][bh * 2 + q], a0, a1, a2, a3,
                                 EL(qb3[q], 2 * j), EL(qb3[q], 2 * j + 1));
                        }
                    }
                }
            }
        }
        __syncthreads();
        if (kt + 2 < NKT) { G1_ISSUE(kt + 2, kt & 1); }
        cp_commit();
    }

    // ---- epilogue: SwiGLU * gate weight -> g_H (tf32-rounded) ----
#pragma unroll
    for (int mi = 0; mi < 2; mi++) {
        int rbase = row0 + wm * 32 + mi * 16 + gId;
#pragma unroll
        for (int half = 0; half < 2; half++) {
            int r = rbase + half * 8;
            if (r < cnt) {
                float wgt = g_wt[e * TMAX + r];
                float* hp = g_H + ((size_t)e * TMAX + r) * FF;
#pragma unroll
                for (int ni = 0; ni < 4; ni++) {
                    int col = n0 + wn * 32 + ni * 8 + tId * 2;
                    float h1a = acc1[mi][ni][half * 2 + 0];
                    float h1b = acc1[mi][ni][half * 2 + 1];
                    float h3a = acc3[mi][ni][half * 2 + 0];
                    float h3b = acc3[mi][ni][half * 2 + 1];
                    float oa = (h1a / (1.f + __expf(-h1a))) * h3a * wgt;
                    float ob = (h1b / (1.f + __expf(-h1b))) * h3b * wgt;
                    uint2 o;
                    o.x = to_tf32(oa); o.y = to_tf32(ob);
                    *(uint2*)(hp + col) = o;
                }
            }
        }
    }
}

// ======================= GEMM2: out[tok] += H W2 =======================
// block 128x128, BK=32, 8 warps (4m x 2n), warp tile 32x64.
// A smem [128][36]; B smem [128 n][36]; stage 36864B; 2 stages -> 2 CTAs/SM.
#define G2_STAGE_F 9216
#define G2_SMEM   (2 * 36864)

__global__ void __launch_bounds__(256, 2)
gemm2_mma(const float* __restrict__ w2t, float* __restrict__ out) {
    const int e    = blockIdx.z;
    const int cnt  = g_cnt[e];
    const int row0 = blockIdx.y * 128;
    if (row0 >= cnt) return;
    const int n0   = blockIdx.x * 128;

    extern __shared__ float sm[];
    const uint32_t sbase = smem_u32(sm);

    const int tid  = threadIdx.x;
    const int lane = tid & 31;
    const int wm   = (tid >> 5) & 3;
    const int wn   = (tid >> 5) >> 2;
    const int gId  = lane >> 2;
    const int tId  = lane & 3;

    const float* asrc[4]; uint32_t adst[4];
#pragma unroll
    for (int j = 0; j < 4; j++) {
        int c = tid + 256 * j;
        int row = c >> 3, kc = c & 7;
        int rr = row0 + row; if (rr >= cnt) rr = cnt - 1;
        asrc[j] = g_H + ((size_t)e * TMAX + rr) * FF + kc * 4;
        adst[j] = 144u * row + 16u * kc;
    }
    const float* bsrc[4]; uint32_t bdst[4];
#pragma unroll
    for (int j = 0; j < 4; j++) {
        int c = tid + 256 * j;
        int n = c >> 3, kc = c & 7;
        bsrc[j] = w2t + (size_t)e * FF * DD + (size_t)(n0 + n) * FF + kc * 4;
        bdst[j] = 18432u + 144u * n + 16u * kc;
    }

#define G2_ISSUE(KT, S) do {                                        \
        uint32_t so_ = sbase + (uint32_t)(S) * 36864u;              \
        int k0_ = (KT) * 32;                                        \
        _Pragma("unroll")                                           \
        for (int j = 0; j < 4; j++) cp16(so_ + adst[j], asrc[j] + k0_); \
        _Pragma("unroll")                                           \
        for (int j = 0; j < 4; j++) cp16(so_ + bdst[j], bsrc[j] + k0_); \
    } while (0)

    G2_ISSUE(0, 0); cp_commit();
    G2_ISSUE(1, 1); cp_commit();

    float acc[2][8][4];
#pragma unroll
    for (int mi = 0; mi < 2; mi++)
#pragma unroll
        for (int ni = 0; ni < 8; ni++)
#pragma unroll
            for (int q = 0; q < 4; q++) acc[mi][ni][q] = 0.f;

    const int NKT = FF / 32;   // 128
    for (int kt = 0; kt < NKT; kt++) {
        cp_wait1();
        __syncthreads();
        const float* As = sm + (kt & 1) * G2_STAGE_F;
        const float* Bs = As + 4608;

#pragma unroll
        for (int h = 0; h < 2; h++) {
            const int kb = 8 * tId + 4 * h;
            uint4 qalo[2], qahi[2];
#pragma unroll
            for (int mi = 0; mi < 2; mi++) {
                int r = wm * 32 + mi * 16 + gId;
                qalo[mi] = *(const uint4*)(As + r * 36 + kb);
                qahi[mi] = *(const uint4*)(As + (r + 8) * 36 + kb);
            }
#pragma unroll
            for (int bh = 0; bh < 2; bh++) {   // ni = bh*4 + q
                uint4 qb[4];
#pragma unroll
                for (int q = 0; q < 4; q++) {
                    int n = wn * 64 + (bh * 4 + q) * 8 + gId;
                    qb[q] = *(const uint4*)(Bs + n * 36 + kb);
                }
#pragma unroll
                for (int j = 0; j < 2; j++) {
#pragma unroll
                    for (int mi = 0; mi < 2; mi++) {
                        uint32_t a0 = EL(qalo[mi], 2 * j),     a1 = EL(qahi[mi], 2 * j);
                        uint32_t a2 = EL(qalo[mi], 2 * j + 1), a3 = EL(qahi[mi], 2 * j + 1);
#pragma unroll
                        for (int q = 0; q < 4; q++)
                            mma8(acc[mi][bh * 4 + q], a0, a1, a2, a3,
                                 EL(qb[q], 2 * j), EL(qb[q], 2 * j + 1));
                    }
                }
            }
        }
        __syncthreads();
        if (kt + 2 < NKT) { G2_ISSUE(kt + 2, kt & 1); }
        cp_commit();
    }

    // ---- epilogue: atomic scatter into out ----
#pragma unroll
    for (int mi = 0; mi < 2; mi++) {
        int rbase = row0 + wm * 32 + mi * 16 + gId;
#pragma unroll
        for (int half = 0; half < 2; half++) {
            int r = rbase + half * 8;
            if (r < cnt) {
                int tok = g_tok[e * TMAX + r];
                float* op = out + (size_t)tok * DD;
#pragma unroll
                for (int ni = 0; ni < 8; ni++) {
                    int col = n0 + wn * 64 + ni * 8 + tId * 2;
                    atomicAdd(&op[col],     acc[mi][ni][half * 2 + 0]);
                    atomicAdd(&op[col + 1], acc[mi][ni][half * 2 + 1]);
                }
            }
        }
    }
}

// ---------------- host ----------------
extern "C" void kernel_launch(void* const* d_in, const int* in_sizes, int n_in,
                              void* d_out, int out_size) {
    const float* x  = (const float*)d_in[0];
    const float* gw = (const float*)d_in[1];
    const float* w1 = (const float*)d_in[2];
    const float* w2 = (const float*)d_in[3];
    const float* w3 = (const float*)d_in[4];
    float* out = (float*)d_out;
    int T = in_sizes[0] / DD;   // 4096

    void *pXc, *pW1t, *pW2t, *pW3t;
    cudaGetSymbolAddress(&pXc,  g_Xc);
    cudaGetSymbolAddress(&pW1t, g_w1t);
    cudaGetSymbolAddress(&pW2t, g_w2t);
    cudaGetSymbolAddress(&pW3t, g_w3t);

    cudaFuncSetAttribute(gemm1_mma, cudaFuncAttributeMaxDynamicSharedMemorySize, G1_SMEM);
    cudaFuncSetAttribute(gemm2_mma, cudaFuncAttributeMaxDynamicSharedMemorySize, G2_SMEM);

    cudaMemsetAsync(out, 0, (size_t)out_size * sizeof(float), 0);
    zero_cnt_kernel<<<1, 32>>>();
    gate_kernel<<<(T * 32 + 255) / 256, 256>>>(x, gw, T);

    conv_tf32_kernel<<<2048, 256>>>((const float4*)x, (float4*)pXc, T * DD / 4);
    trans_tf32_kernel<<<dim3(FF / 32, DD / 32, NE), 256>>>(w1, (float*)pW1t, DD, FF);
    trans_tf32_kernel<<<dim3(FF / 32, DD / 32, NE), 256>>>(w3, (float*)pW3t, DD, FF);
    trans_tf32_kernel<<<dim3(DD / 32, FF / 32, NE), 256>>>(w2, (float*)pW2t, FF, DD);

    dim3 g1(FF / 64, TMAX / 128, NE);
    gemm1_mma<<<g1, 256, G1_SMEM>>>((const float*)pXc, (const float*)pW1t, (const float*)pW3t);

    dim3 g2(DD / 128, TMAX / 128, NE);
    gemm2_mma<<<g2, 256, G2_SMEM>>>((const float*)pW2t, out);
}

// round 7
// speedup vs baseline: 1.2214x; 1.2214x over previous
#include <cuda_runtime.h>
#include <cstdint>
#include <math.h>

#define NE   8
#define DD   1024
#define FF   4096
#define TMAX 4096

// ---------------- device scratch ----------------
__device__ int   g_cnt[NE];
__device__ int   g_tok[NE * TMAX];
__device__ float g_wt [NE * TMAX];
__device__ float g_Xc [(size_t)TMAX * DD];          // tf32-rounded x
__device__ float g_w1c[(size_t)NE * DD * FF];       // tf32-rounded w1
__device__ float g_w3c[(size_t)NE * DD * FF];
__device__ float g_w2c[(size_t)NE * FF * DD];
__device__ float g_H  [(size_t)NE * TMAX * FF];     // SwiGLU acts (tf32-rounded)

// ---------------- helpers ----------------
__device__ __forceinline__ uint32_t smem_u32(const void* p) {
    uint32_t a;
    asm("{ .reg .u64 t; cvta.to.shared.u64 t, %1; cvt.u32.u64 %0, t; }" : "=r"(a) : "l"(p));
    return a;
}
__device__ __forceinline__ void cp16(uint32_t dst, const void* src) {
    asm volatile("cp.async.cg.shared.global [%0], [%1], 16;" :: "r"(dst), "l"(src));
}
__device__ __forceinline__ void cp_commit() { asm volatile("cp.async.commit_group;"); }
__device__ __forceinline__ void cp_wait1()  { asm volatile("cp.async.wait_group 1;"); }

__device__ __forceinline__ uint32_t to_tf32(float f) {
    uint32_t u;
    asm("cvt.rna.tf32.f32 %0, %1;" : "=r"(u) : "f"(f));
    return u;
}
__device__ __forceinline__ void mma8(float* c, const uint32_t* a, const uint32_t* b) {
    asm volatile(
        "mma.sync.aligned.m16n8k8.row.col.f32.tf32.tf32.f32 "
        "{%0,%1,%2,%3}, {%4,%5,%6,%7}, {%8,%9}, {%0,%1,%2,%3};"
        : "+f"(c[0]), "+f"(c[1]), "+f"(c[2]), "+f"(c[3])
        : "r"(a[0]), "r"(a[1]), "r"(a[2]), "r"(a[3]), "r"(b[0]), "r"(b[1]));
}

// ---------------- small kernels ----------------
__global__ void zero_cnt_kernel() { if (threadIdx.x < NE) g_cnt[threadIdx.x] = 0; }

__global__ void conv_tf32_kernel(const float4* __restrict__ s, float4* __restrict__ d, int n4) {
    int i = blockIdx.x * blockDim.x + threadIdx.x;
    int stride = gridDim.x * blockDim.x;
    for (; i < n4; i += stride) {
        float4 v = s[i];
        uint4 o;
        o.x = to_tf32(v.x); o.y = to_tf32(v.y); o.z = to_tf32(v.z); o.w = to_tf32(v.w);
        d[i] = *(float4*)&o;
    }
}

__global__ void gate_kernel(const float* __restrict__ x,
                            const float* __restrict__ gw, int T) {
    int warp = (blockIdx.x * blockDim.x + threadIdx.x) >> 5;
    int lane = threadIdx.x & 31;
    if (warp >= T) return;
    const float* xr = x + (size_t)warp * DD;
    float acc[NE];
#pragma unroll
    for (int e = 0; e < NE; e++) acc[e] = 0.f;
    for (int d = lane; d < DD; d += 32) {
        float xv = xr[d];
        const float* g = gw + (size_t)d * NE;
#pragma unroll
        for (int e = 0; e < NE; e++) acc[e] += xv * g[e];
    }
#pragma unroll
    for (int e = 0; e < NE; e++)
#pragma unroll
        for (int off = 16; off > 0; off >>= 1)
            acc[e] += __shfl_xor_sync(0xffffffffu, acc[e], off);
    if (lane == 0) {
        int i0 = 0; float v0 = acc[0];
#pragma unroll
        for (int e = 1; e < NE; e++) if (acc[e] > v0) { v0 = acc[e]; i0 = e; }
        int i1 = -1; float v1 = -3.0e38f;
#pragma unroll
        for (int e = 0; e < NE; e++)
            if (e != i0 && acc[e] > v1) { v1 = acc[e]; i1 = e; }
        float t  = expf(v1 - v0);
        float w0 = 1.f / (1.f + t);
        float w1 = t / (1.f + t);
        int s0 = atomicAdd(&g_cnt[i0], 1);
        g_tok[i0 * TMAX + s0] = warp; g_wt[i0 * TMAX + s0] = w0;
        int s1 = atomicAdd(&g_cnt[i1], 1);
        g_tok[i1 * TMAX + s1] = warp; g_wt[i1 * TMAX + s1] = w1;
    }
}

// ======================= GEMM1: H = silu(X W1) * (X W3) * wgt =======================
// block 128x64, BK=32, 8 warps (4m x 2n), warp tile 32x32, dual accumulators.
// smem stage: A[128][36] (18432B) + B1[32][72] (9216B) + B3[32][72] -> 36864B.
// 2 stages = 72KB -> 2 CTAs/SM.
// Rasterization: blockIdx.x = M-TILE (fast) so consecutive CTAs share the B tile;
// A (gathered X, ~4MB/expert) stays L2-resident -> weights read from DRAM once.
#define G1_STAGE_F 9216     // floats per stage
#define G1_SMEM   (2 * 36864)

__global__ void __launch_bounds__(256, 2)
gemm1_mma(const float* __restrict__ Xc,
          const float* __restrict__ w1c,
          const float* __restrict__ w3c) {
    const int e    = blockIdx.z;
    const int cnt  = g_cnt[e];
    const int row0 = blockIdx.x * 128;   // m-tile: FAST index
    if (row0 >= cnt) return;
    const int n0   = blockIdx.y * 64;    // n-tile: SLOW index

    extern __shared__ float sm[];
    const uint32_t sbase = smem_u32(sm);

    const int tid  = threadIdx.x;
    const int lane = tid & 31;
    const int wm   = (tid >> 5) & 3;     // warp m: 0..3  (32 rows each)
    const int wn   = (tid >> 5) >> 2;    // warp n: 0..1  (32 cols each)
    const int gId  = lane >> 2;          // 0..7
    const int tId  = lane & 3;           // 0..3

    // ---- cp.async source/dst precompute ----
    const float* asrc[4]; uint32_t adst[4];
#pragma unroll
    for (int j = 0; j < 4; j++) {
        int c = tid + 256 * j;
        int row = c >> 3, kc = c & 7;
        int rr = row0 + row; if (rr >= cnt) rr = cnt - 1;
        int tok = g_tok[e * TMAX + rr];
        asrc[j] = Xc + (size_t)tok * DD + kc * 4;
        adst[j] = 144u * row + 16u * kc;
    }
    const float* bsrc[4]; uint32_t bdst[4];
#pragma unroll
    for (int j = 0; j < 4; j++) {
        int c = tid + 256 * j;
        int mat = c >> 9, cc = c & 511;
        int row = cc >> 4, nc = cc & 15;
        const float* w = mat ? w3c : w1c;
        bsrc[j] = w + (size_t)e * DD * FF + (size_t)row * FF + n0 + nc * 4;
        bdst[j] = 18432u + (uint32_t)mat * 9216u + row * 288u + nc * 16u;
    }

#define G1_ISSUE(KT, S) do {                                        \
        uint32_t so_ = sbase + (uint32_t)(S) * 36864u;              \
        int k0_ = (KT) * 32;                                        \
        _Pragma("unroll")                                           \
        for (int j = 0; j < 4; j++) cp16(so_ + adst[j], asrc[j] + k0_); \
        _Pragma("unroll")                                           \
        for (int j = 0; j < 4; j++) cp16(so_ + bdst[j], bsrc[j] + (size_t)k0_ * FF); \
    } while (0)

    G1_ISSUE(0, 0); cp_commit();
    G1_ISSUE(1, 1); cp_commit();

    float acc1[2][4][4], acc3[2][4][4];
#pragma unroll
    for (int mi = 0; mi < 2; mi++)
#pragma unroll
        for (int ni = 0; ni < 4; ni++)
#pragma unroll
            for (int q = 0; q < 4; q++) { acc1[mi][ni][q] = 0.f; acc3[mi][ni][q] = 0.f; }

    const int NKT = DD / 32;   // 32
    for (int kt = 0; kt < NKT; kt++) {
        cp_wait1();
        __syncthreads();
        const uint32_t* As = (const uint32_t*)(sm + (kt & 1) * G1_STAGE_F);
        const uint32_t* B1 = As + 4608;
        const uint32_t* B3 = As + 6912;

#pragma unroll
        for (int ks = 0; ks < 4; ks++) {
            const int kb = ks * 8;
            uint32_t a[2][4], b1[4][2], b3[4][2];
#pragma unroll
            for (int mi = 0; mi < 2; mi++) {
                int r = wm * 32 + mi * 16 + gId;
                int c = kb + tId;
                a[mi][0] = As[r * 36 + c];
                a[mi][1] = As[(r + 8) * 36 + c];
                a[mi][2] = As[r * 36 + c + 4];
                a[mi][3] = As[(r + 8) * 36 + c + 4];
            }
#pragma unroll
            for (int ni = 0; ni < 4; ni++) {
                int n = wn * 32 + ni * 8 + gId;
                int k = kb + tId;
                b1[ni][0] = B1[k * 72 + n];
                b1[ni][1] = B1[(k + 4) * 72 + n];
                b3[ni][0] = B3[k * 72 + n];
                b3[ni][1] = B3[(k + 4) * 72 + n];
            }
#pragma unroll
            for (int mi = 0; mi < 2; mi++)
#pragma unroll
                for (int ni = 0; ni < 4; ni++) {
                    mma8(acc1[mi][ni], a[mi], b1[ni]);
                    mma8(acc3[mi][ni], a[mi], b3[ni]);
                }
        }
        __syncthreads();
        if (kt + 2 < NKT) { G1_ISSUE(kt + 2, kt & 1); }
        cp_commit();
    }

    // ---- epilogue: SwiGLU * gate weight -> g_H (tf32-rounded) ----
#pragma unroll
    for (int mi = 0; mi < 2; mi++) {
        int rbase = row0 + wm * 32 + mi * 16 + gId;
#pragma unroll
        for (int half = 0; half < 2; half++) {
            int r = rbase + half * 8;
            if (r < cnt) {
                float wgt = g_wt[e * TMAX + r];
                float* hp = g_H + ((size_t)e * TMAX + r) * FF;
#pragma unroll
                for (int ni = 0; ni < 4; ni++) {
                    int col = n0 + wn * 32 + ni * 8 + tId * 2;
                    float h1a = acc1[mi][ni][half * 2 + 0];
                    float h1b = acc1[mi][ni][half * 2 + 1];
                    float h3a = acc3[mi][ni][half * 2 + 0];
                    float h3b = acc3[mi][ni][half * 2 + 1];
                    float oa = (h1a / (1.f + __expf(-h1a))) * h3a * wgt;
                    float ob = (h1b / (1.f + __expf(-h1b))) * h3b * wgt;
                    uint2 o;
                    o.x = to_tf32(oa); o.y = to_tf32(ob);
                    *(uint2*)(hp + col) = o;
                }
            }
        }
    }
}

// ======================= GEMM2: out[tok] += H W2 =======================
// block 128x128, BK=32, 8 warps (4m x 2n), warp tile 32x64.
// smem stage: A[128][36] (18432B) + B[32][136] (17408B) -> 35840B; 2 stages -> 2 CTAs/SM.
// Rasterization: blockIdx.x = M-TILE (fast), n-tile slow -> H L2-resident, W2 read once.
#define G2_STAGE_F 8960
#define G2_SMEM   (2 * 35840)

__global__ void __launch_bounds__(256, 2)
gemm2_mma(const float* __restrict__ w2c, float* __restrict__ out) {
    const int e    = blockIdx.z;
    const int cnt  = g_cnt[e];
    const int row0 = blockIdx.x * 128;   // m-tile: FAST index
    if (row0 >= cnt) return;
    const int n0   = blockIdx.y * 128;   // n-tile: SLOW index

    extern __shared__ float sm[];
    const uint32_t sbase = smem_u32(sm);

    const int tid  = threadIdx.x;
    const int lane = tid & 31;
    const int wm   = (tid >> 5) & 3;
    const int wn   = (tid >> 5) >> 2;
    const int gId  = lane >> 2;
    const int tId  = lane & 3;

    const float* asrc[4]; uint32_t adst[4];
#pragma unroll
    for (int j = 0; j < 4; j++) {
        int c = tid + 256 * j;
        int row = c >> 3, kc = c & 7;
        int rr = row0 + row; if (rr >= cnt) rr = cnt - 1;
        asrc[j] = g_H + ((size_t)e * TMAX + rr) * FF + kc * 4;
        adst[j] = 144u * row + 16u * kc;
    }
    const float* bsrc[4]; uint32_t bdst[4];
#pragma unroll
    for (int j = 0; j < 4; j++) {
        int c = tid + 256 * j;
        int row = c >> 5, nc = c & 31;
        bsrc[j] = w2c + (size_t)e * FF * DD + (size_t)row * DD + n0 + nc * 4;
        bdst[j] = 18432u + row * 544u + nc * 16u;
    }

#define G2_ISSUE(KT, S) do {                                        \
        uint32_t so_ = sbase + (uint32_t)(S) * 35840u;              \
        int k0_ = (KT) * 32;                                        \
        _Pragma("unroll")                                           \
        for (int j = 0; j < 4; j++) cp16(so_ + adst[j], asrc[j] + k0_); \
        _Pragma("unroll")                                           \
        for (int j = 0; j < 4; j++) cp16(so_ + bdst[j], bsrc[j] + (size_t)k0_ * DD); \
    } while (0)

    G2_ISSUE(0, 0); cp_commit();
    G2_ISSUE(1, 1); cp_commit();

    float acc[2][8][4];
#pragma unroll
    for (int mi = 0; mi < 2; mi++)
#pragma unroll
        for (int ni = 0; ni < 8; ni++)
#pragma unroll
            for (int q = 0; q < 4; q++) acc[mi][ni][q] = 0.f;

    const int NKT = FF / 32;   // 128
    for (int kt = 0; kt < NKT; kt++) {
        cp_wait1();
        __syncthreads();
        const uint32_t* As = (const uint32_t*)(sm + (kt & 1) * G2_STAGE_F);
        const uint32_t* Bs = As + 4608;

#pragma unroll
        for (int ks = 0; ks < 4; ks++) {
            const int kb = ks * 8;
            uint32_t a[2][4], b[8][2];
#pragma unroll
            for (int mi = 0; mi < 2; mi++) {
                int r = wm * 32 + mi * 16 + gId;
                int c = kb + tId;
                a[mi][0] = As[r * 36 + c];
                a[mi][1] = As[(r + 8) * 36 + c];
                a[mi][2] = As[r * 36 + c + 4];
                a[mi][3] = As[(r + 8) * 36 + c + 4];
            }
#pragma unroll
            for (int ni = 0; ni < 8; ni++) {
                int n = wn * 64 + ni * 8 + gId;
                int k = kb + tId;
                b[ni][0] = Bs[k * 136 + n];
                b[ni][1] = Bs[(k + 4) * 136 + n];
            }
#pragma unroll
            for (int mi = 0; mi < 2; mi++)
#pragma unroll
                for (int ni = 0; ni < 8; ni++)
                    mma8(acc[mi][ni], a[mi], b[ni]);
        }
        __syncthreads();
        if (kt + 2 < NKT) { G2_ISSUE(kt + 2, kt & 1); }
        cp_commit();
    }

    // ---- epilogue: atomic scatter into out ----
#pragma unroll
    for (int mi = 0; mi < 2; mi++) {
        int rbase = row0 + wm * 32 + mi * 16 + gId;
#pragma unroll
        for (int half = 0; half < 2; half++) {
            int r = rbase + half * 8;
            if (r < cnt) {
                int tok = g_tok[e * TMAX + r];
                float* op = out + (size_t)tok * DD;
#pragma unroll
                for (int ni = 0; ni < 8; ni++) {
                    int col = n0 + wn * 64 + ni * 8 + tId * 2;
                    atomicAdd(&op[col],     acc[mi][ni][half * 2 + 0]);
                    atomicAdd(&op[col + 1], acc[mi][ni][half * 2 + 1]);
                }
            }
        }
    }
}

// ---------------- host ----------------
extern "C" void kernel_launch(void* const* d_in, const int* in_sizes, int n_in,
                              void* d_out, int out_size) {
    const float* x  = (const float*)d_in[0];
    const float* gw = (const float*)d_in[1];
    const float* w1 = (const float*)d_in[2];
    const float* w2 = (const float*)d_in[3];
    const float* w3 = (const float*)d_in[4];
    float* out = (float*)d_out;
    int T = in_sizes[0] / DD;   // 4096

    void *pXc, *pW1c, *pW2c, *pW3c;
    cudaGetSymbolAddress(&pXc,  g_Xc);
    cudaGetSymbolAddress(&pW1c, g_w1c);
    cudaGetSymbolAddress(&pW2c, g_w2c);
    cudaGetSymbolAddress(&pW3c, g_w3c);

    cudaFuncSetAttribute(gemm1_mma, cudaFuncAttributeMaxDynamicSharedMemorySize, G1_SMEM);
    cudaFuncSetAttribute(gemm2_mma, cudaFuncAttributeMaxDynamicSharedMemorySize, G2_SMEM);

    cudaMemsetAsync(out, 0, (size_t)out_size * sizeof(float), 0);
    zero_cnt_kernel<<<1, 32>>>();
    gate_kernel<<<(T * 32 + 255) / 256, 256>>>(x, gw, T);

    // tf32-round inputs & weights (unbiased rna)
    int n4x = T * DD / 4;
    int n4w = NE * DD * FF / 4;
    conv_tf32_kernel<<<2048, 256>>>((const float4*)x,  (float4*)pXc,  n4x);
    conv_tf32_kernel<<<4096, 256>>>((const float4*)w1, (float4*)pW1c, n4w);
    conv_tf32_kernel<<<4096, 256>>>((const float4*)w3, (float4*)pW3c, n4w);
    conv_tf32_kernel<<<4096, 256>>>((const float4*)w2, (float4*)pW2c, n4w);

    // m-tile fast, n-tile slow: weights stream from DRAM once, A stays in L2
    dim3 g1(TMAX / 128, FF / 64, NE);
    gemm1_mma<<<g1, 256, G1_SMEM>>>((const float*)pXc, (const float*)pW1c, (const float*)pW3c);

    dim3 g2(TMAX / 128, DD / 128, NE);
    gemm2_mma<<<g2, 256, G2_SMEM>>>((const float*)pW2c, out);
}